// round 14
// baseline (speedup 1.0000x reference)
#include <cuda_runtime.h>
#include <cuda_bf16.h>

// RerankLoss: per-row pairwise hinge over (pos, neg) pairs, exact bucketed algorithm.
// Row length L = 512 fixed. One warp per row.

#define L_LEN   512
#define NB      128          // bins
#define WARPS   4            // warps (rows) per CTA
#define LO_F    (-6.0f)
#define INVW_F  (NB / 12.0f) // 1/binwidth, range [-6, 6)

static __device__ float g_row[4096];   // per-row loss scratch (B <= 4096)

__global__ void __launch_bounds__(32 * WARPS)
rerank_rows_kernel(const float* __restrict__ scores,
                   const int*   __restrict__ labels,
                   int B)
{
    __shared__ int   s_cnt [WARPS][NB];
    __shared__ float s_sum [WARPS][NB];
    __shared__ int   s_prefC[WARPS][NB + 1];
    __shared__ float s_prefS[WARPS][NB];
    __shared__ int   s_cur [WARPS][NB];
    __shared__ float s_pos [WARPS][L_LEN];

    const int w    = threadIdx.x >> 5;
    const int lane = threadIdx.x & 31;
    const int row  = blockIdx.x * WARPS + w;
    if (row >= B) return;   // whole warp exits together; only __syncwarp used below

    // ---- load 16 values + 16 label bits per lane (vectorized, contiguous per lane)
    const float4* rv4 = reinterpret_cast<const float4*>(scores + (size_t)row * L_LEN) + lane * 4;
    const int4*   rl4 = reinterpret_cast<const int4*>  (labels + (size_t)row * L_LEN) + lane * 4;

    float v[16];
    unsigned pm = 0u;        // bit k set -> element k has label 1 (positive)
    #pragma unroll
    for (int q = 0; q < 4; q++) {
        float4 fv = rv4[q];
        int4   iv = rl4[q];
        v[q * 4 + 0] = fv.x; v[q * 4 + 1] = fv.y;
        v[q * 4 + 2] = fv.z; v[q * 4 + 3] = fv.w;
        if (iv.x) pm |= 1u << (q * 4 + 0);
        if (iv.y) pm |= 1u << (q * 4 + 1);
        if (iv.z) pm |= 1u << (q * 4 + 2);
        if (iv.w) pm |= 1u << (q * 4 + 3);
    }

    // ---- zero histogram
    #pragma unroll
    for (int m = 0; m < NB / 32; m++) {
        s_cnt[w][lane + m * 32] = 0;
        s_sum[w][lane + m * 32] = 0.0f;
    }
    __syncwarp();

    // ---- histogram positives: per-bin count and value-sum
    #pragma unroll
    for (int k = 0; k < 16; k++) {
        if (pm & (1u << k)) {
            int b = (int)((v[k] - LO_F) * INVW_F);
            b = max(0, min(NB - 1, b));
            atomicAdd(&s_cnt[w][b], 1);
            atomicAdd(&s_sum[w][b], v[k]);
        }
    }
    __syncwarp();

    // ---- exclusive prefix scan over NB bins (counts + sums), 4 bins per lane
    const int BPL = NB / 32;
    int   cloc[BPL]; float sloc[BPL];
    int   ctot = 0;  float stot = 0.0f;
    #pragma unroll
    for (int m = 0; m < BPL; m++) {
        cloc[m] = ctot; sloc[m] = stot;
        ctot += s_cnt[w][lane * BPL + m];
        stot += s_sum[w][lane * BPL + m];
    }
    int cinc = ctot; float sinc = stot;
    #pragma unroll
    for (int off = 1; off < 32; off <<= 1) {
        int   cn = __shfl_up_sync(0xffffffffu, cinc, off);
        float sn = __shfl_up_sync(0xffffffffu, sinc, off);
        if (lane >= off) { cinc += cn; sinc += sn; }
    }
    const int   cbase = cinc - ctot;   // exclusive base for this lane's bins
    const float sbase = sinc - stot;
    #pragma unroll
    for (int m = 0; m < BPL; m++) {
        s_prefC[w][lane * BPL + m] = cbase + cloc[m];
        s_prefS[w][lane * BPL + m] = sbase + sloc[m];
        s_cur  [w][lane * BPL + m] = cbase + cloc[m];
    }
    if (lane == 31) s_prefC[w][NB] = cinc;   // total n_pos
    __syncwarp();

    const int n_pos = s_prefC[w][NB];

    // ---- scatter positives into bucketed array (counting sort)
    #pragma unroll
    for (int k = 0; k < 16; k++) {
        if (pm & (1u << k)) {
            int b = (int)((v[k] - LO_F) * INVW_F);
            b = max(0, min(NB - 1, b));
            int p = atomicAdd(&s_cur[w][b], 1);
            s_pos[w][p] = v[k];
        }
    }
    __syncwarp();

    // ---- negatives: closed form over bins below + exact relu over boundary bin
    float acc = 0.0f;
    #pragma unroll
    for (int k = 0; k < 16; k++) {
        if (!(pm & (1u << k))) {
            float t = v[k] + 1.0f;                 // hinge threshold
            int j = (int)((t - LO_F) * INVW_F);
            j = max(0, min(NB - 1, j));
            int c0 = s_prefC[w][j];
            int c1 = s_prefC[w][j + 1];
            acc += (float)c0 * t - s_prefS[w][j];  // all p in bins < j satisfy p < t
            for (int q = c0; q < c1; q++)          // exact relu in boundary bin
                acc += fmaxf(t - s_pos[w][q], 0.0f);
        }
    }

    // ---- warp reduce
    #pragma unroll
    for (int off = 16; off; off >>= 1)
        acc += __shfl_xor_sync(0xffffffffu, acc, off);

    if (lane == 0) {
        float npairs = (float)n_pos * (float)(L_LEN - n_pos);
        g_row[row] = acc / fmaxf(npairs, 1.0f);
    }
}

__global__ void rerank_reduce_kernel(float* __restrict__ out, int B)
{
    __shared__ float sm[256];
    float a = 0.0f;
    for (int i = threadIdx.x; i < B; i += 256) a += g_row[i];
    sm[threadIdx.x] = a;
    __syncthreads();
    #pragma unroll
    for (int s = 128; s > 0; s >>= 1) {
        if (threadIdx.x < s) sm[threadIdx.x] += sm[threadIdx.x + s];
        __syncthreads();
    }
    if (threadIdx.x == 0) out[0] = sm[0] / (float)B;
}

extern "C" void kernel_launch(void* const* d_in, const int* in_sizes, int n_in,
                              void* d_out, int out_size)
{
    const float* scores = (const float*)d_in[0];
    const int*   labels = (const int*)d_in[1];
    const int B = in_sizes[0] / L_LEN;

    rerank_rows_kernel<<<(B + WARPS - 1) / WARPS, 32 * WARPS>>>(scores, labels, B);
    rerank_reduce_kernel<<<1, 256>>>((float*)d_out, B);
}